// round 9
// baseline (speedup 1.0000x reference)
#include <cuda_runtime.h>

#define FULL 0xffffffffu

// ---------------- scratch (device globals; no allocations) ----------------
__device__ float g_t1q[4 * 1024 * 128];
__device__ float g_t1k[4 * 1024 * 128];
__device__ float g_t1v[4 * 1024 * 128];
__device__ float g_t2q[4 * 4096 * 128];
__device__ float g_t2k[4 * 4096 * 128];
__device__ float g_t2v[4 * 4096 * 128];

__device__ float g_msg0[4 * 256  * 128];
__device__ float g_msg1[4 * 1024 * 128];
__device__ float g_msg2[4 * 4096 * 128];

__device__ float g_ts0[4 * 256 * 8 * 16];
__device__ int   g_ti0[4 * 256 * 8 * 16];
__device__ float g_ts1[4 * 1024 * 8 * 8];
__device__ int   g_ti1[4 * 1024 * 8 * 8];

__device__ __forceinline__ void load16(const float* __restrict__ src, float* dst) {
    const float4* s4 = reinterpret_cast<const float4*>(src);
    float4 r0 = s4[0], r1 = s4[1], r2 = s4[2], r3 = s4[3];
    dst[0]  = r0.x; dst[1]  = r0.y; dst[2]  = r0.z; dst[3]  = r0.w;
    dst[4]  = r1.x; dst[5]  = r1.y; dst[6]  = r1.z; dst[7]  = r1.w;
    dst[8]  = r2.x; dst[9]  = r2.y; dst[10] = r2.z; dst[11] = r2.w;
    dst[12] = r3.x; dst[13] = r3.y; dst[14] = r3.z; dst[15] = r3.w;
}

// ---------------- [B,C,S] -> [B,S,C]  (C=128) tiled transpose -------------
__global__ __launch_bounds__(256) void transpose_kernel(const float* __restrict__ src,
                                                        int which, int S) {
    __shared__ float tile[32][33];
    float* dst;
    switch (which) {
        case 0: dst = g_t1q; break;
        case 1: dst = g_t1k; break;
        case 2: dst = g_t1v; break;
        case 3: dst = g_t2q; break;
        case 4: dst = g_t2k; break;
        default: dst = g_t2v; break;
    }
    int b  = blockIdx.z;
    int c0 = blockIdx.y << 5;
    int s0 = blockIdx.x << 5;
    const float* sp = src + (size_t)b * 128 * S;
    float* dp = dst + (size_t)b * S * 128;
    int tx = threadIdx.x, ty = threadIdx.y;   // (32,8)
#pragma unroll
    for (int i = 0; i < 32; i += 8)
        tile[ty + i][tx] = sp[(size_t)(c0 + ty + i) * S + s0 + tx];
    __syncthreads();
#pragma unroll
    for (int i = 0; i < 32; i += 8)
        dp[(size_t)(s0 + ty + i) * 128 + c0 + tx] = tile[tx][ty + i];
}

// ---------------- level 0: dense coarse attention --------------------------
// grid = B*N*16 blocks (16 query-tiles of 16), 256 threads
__global__ __launch_bounds__(256) void lvl0_kernel(const float* __restrict__ q0,
                                                   const float* __restrict__ k0,
                                                   const float* __restrict__ v0) {
    __shared__ float sK[256 * 17];   // K (then V), padded
    __shared__ float sA[16 * 256];   // scores / softmax / masked A
    __shared__ float sQ[16 * 16];

    int blk = blockIdx.x;
    int qt = blk & 15;
    int n  = (blk >> 4) & 7;
    int b  = blk >> 7;
    int t  = threadIdx.x;

    const float* kh = k0 + ((size_t)b * 128 + n * 16) * 256;
    const float* qh = q0 + ((size_t)b * 128 + n * 16) * 256;

#pragma unroll
    for (int i = 0; i < 16; i++) {
        int idx = i * 256 + t;
        int d = idx >> 8, s = idx & 255;
        sK[s * 17 + d] = kh[d * 256 + s];
    }
    {
        int qq = t >> 4, d = t & 15;
        sQ[qq * 16 + d] = qh[d * 256 + qt * 16 + qq];
    }
    __syncthreads();

    int qq = t >> 4, spt = t & 15;
    for (int i = 0; i < 16; i++) {
        int s = spt + 16 * i;
        float acc = 0.f;
#pragma unroll
        for (int d = 0; d < 16; d++) acc = fmaf(sQ[qq * 16 + d], sK[s * 17 + d], acc);
        sA[qq * 256 + s] = acc * 0.25f;
    }
    __syncthreads();

    int warp = t >> 5, lane = t & 31;
#pragma unroll
    for (int rr = 0; rr < 2; rr++) {
        int r = warp + rr * 8;
        float* row = sA + r * 256;
        float v[8];
#pragma unroll
        for (int j = 0; j < 8; j++) v[j] = row[lane + 32 * j];
        float m = v[0];
#pragma unroll
        for (int j = 1; j < 8; j++) m = fmaxf(m, v[j]);
#pragma unroll
        for (int off = 16; off; off >>= 1) m = fmaxf(m, __shfl_xor_sync(FULL, m, off));
        float sum = 0.f;
#pragma unroll
        for (int j = 0; j < 8; j++) { v[j] = __expf(v[j] - m); sum += v[j]; }
#pragma unroll
        for (int off = 16; off; off >>= 1) sum += __shfl_xor_sync(FULL, sum, off);
        float inv = 1.f / sum;
#pragma unroll
        for (int j = 0; j < 8; j++) { v[j] *= inv; row[lane + 32 * j] = v[j]; }

        // top-16 (record then zero = mask)
        int l = qt * 16 + r;
        size_t ob = (((size_t)b * 256 + l) * 8 + n) * 16;
        for (int k = 0; k < 16; k++) {
            float bv = v[0]; int bj = 0;
#pragma unroll
            for (int j = 1; j < 8; j++) if (v[j] > bv) { bv = v[j]; bj = j; }
            int bi = lane + 32 * bj;
#pragma unroll
            for (int off = 16; off; off >>= 1) {
                float ov = __shfl_xor_sync(FULL, bv, off);
                int   oi = __shfl_xor_sync(FULL, bi, off);
                if (ov > bv || (ov == bv && oi < bi)) { bv = ov; bi = oi; }
            }
            if (lane == (bi & 31)) { v[bi >> 5] = -1.f; row[bi] = 0.f; }
            if (lane == 0) { g_ts0[ob + k] = bv; g_ti0[ob + k] = bi; }
        }
    }
    __syncthreads();

    const float* vh = v0 + ((size_t)b * 128 + n * 16) * 256;
#pragma unroll
    for (int i = 0; i < 16; i++) {
        int idx = i * 256 + t;
        int d = idx >> 8, s = idx & 255;
        sK[s * 17 + d] = vh[d * 256 + s];
    }
    __syncthreads();
    {
        int d = t & 15;
        const float* arow = sA + qq * 256;
        float acc = 0.f;
        for (int s = 0; s < 256; s++) acc = fmaf(arow[s], sK[s * 17 + d], acc);
        g_msg0[((size_t)b * 256 + qt * 16 + qq) * 128 + n * 16 + d] = acc;
    }
}

// ---------------- level 1: fine attention (16 parents -> 64 keys) ----------
// grid = B*256 quads, 256 threads (warp per head). Each lane owns keys lane, lane+32.
__global__ __launch_bounds__(256) void lvl1_kernel() {
    __shared__ float sKV[8][64 * 17];
    __shared__ float sAm[8][4 * 64];
    __shared__ float sQ [8][64];
    __shared__ int   sKey[8][64];
    __shared__ float sPar[8][16];

    int blk = blockIdx.x;
    int L = blk & 255, b = blk >> 8;
    int Y = L >> 4, X = L & 15;
    int n = threadIdx.x >> 5, lane = threadIdx.x & 31;
    float* kv = sKV[n];
    float* A  = sAm[n];
    float* Qs = sQ[n];

    if (lane < 16) {
        size_t pb = (((size_t)b * 256 + L) * 8 + n) * 16 + lane;
        sPar[n][lane] = g_ts0[pb];
        int pi = g_ti0[pb];
        int base = (pi >> 4) * 64 + (pi & 15) * 2;   // (2*y0)*32 + 2*x0
        sKey[n][lane * 4 + 0] = base;
        sKey[n][lane * 4 + 1] = base + 1;
        sKey[n][lane * 4 + 2] = base + 32;
        sKey[n][lane * 4 + 3] = base + 33;
    }
    __syncwarp();

    const float* kb = g_t1k + (size_t)b * 1024 * 128 + n * 16;
#pragma unroll
    for (int j = 0; j < 2; j++) {
        int k = lane + 32 * j;
        load16(kb + (size_t)sKey[n][k] * 128, kv + k * 17);
    }
    const float* qb = g_t1q + (size_t)b * 1024 * 128 + n * 16;
#pragma unroll
    for (int rep = 0; rep < 2; rep++) {
        int jj = lane + 32 * rep;
        int tq = jj >> 4, d = jj & 15;
        int tok = (2 * Y + (tq >> 1)) * 32 + 2 * X + (tq & 1);
        Qs[jj] = qb[(size_t)tok * 128 + d];
    }
    __syncwarp();

    float a0[4], a1[4];
#pragma unroll
    for (int tq = 0; tq < 4; tq++) {
        float acc0 = 0.f, acc1 = 0.f;
#pragma unroll
        for (int d = 0; d < 16; d++) {
            float qv = Qs[tq * 16 + d];
            acc0 = fmaf(qv, kv[lane * 17 + d], acc0);
            acc1 = fmaf(qv, kv[(lane + 32) * 17 + d], acc1);
        }
        a0[tq] = acc0 * 0.25f;
        a1[tq] = acc1 * 0.25f;
    }
    float ps0 = sPar[n][lane >> 2];
    float ps1 = sPar[n][8 + (lane >> 2)];
#pragma unroll
    for (int tq = 0; tq < 4; tq++) {
        float m = a0[tq];
        m = fmaxf(m, __shfl_xor_sync(FULL, m, 1));
        m = fmaxf(m, __shfl_xor_sync(FULL, m, 2));
        float e = __expf(a0[tq] - m);
        float s = e;
        s += __shfl_xor_sync(FULL, s, 1);
        s += __shfl_xor_sync(FULL, s, 2);
        a0[tq] = e / s * ps0;

        m = a1[tq];
        m = fmaxf(m, __shfl_xor_sync(FULL, m, 1));
        m = fmaxf(m, __shfl_xor_sync(FULL, m, 2));
        e = __expf(a1[tq] - m);
        s = e;
        s += __shfl_xor_sync(FULL, s, 1);
        s += __shfl_xor_sync(FULL, s, 2);
        a1[tq] = e / s * ps1;

        A[tq * 64 + lane]      = a0[tq];
        A[tq * 64 + 32 + lane] = a1[tq];
    }

    // top-8 of 64 per quad-position (record + mask)
#pragma unroll
    for (int tq = 0; tq < 4; tq++) {
        int tok = (2 * Y + (tq >> 1)) * 32 + 2 * X + (tq & 1);
        size_t ob = (((size_t)b * 1024 + tok) * 8 + n) * 8;
        float r0v = a0[tq], r1v = a1[tq];
        for (int k = 0; k < 8; k++) {
            float bv; int bi;
            if (r0v >= r1v) { bv = r0v; bi = lane; }
            else            { bv = r1v; bi = lane + 32; }
#pragma unroll
            for (int off = 16; off; off >>= 1) {
                float ov = __shfl_xor_sync(FULL, bv, off);
                int   oi = __shfl_xor_sync(FULL, bi, off);
                if (ov > bv || (ov == bv && oi < bi)) { bv = ov; bi = oi; }
            }
            if (lane == (bi & 31)) {
                if (bi >= 32) r1v = -1.f; else r0v = -1.f;
                A[tq * 64 + bi] = 0.f;
            }
            if (lane == 0) { g_ts1[ob + k] = bv; g_ti1[ob + k] = sKey[n][bi]; }
        }
    }
    __syncwarp();

    const float* vb = g_t1v + (size_t)b * 1024 * 128 + n * 16;
#pragma unroll
    for (int j = 0; j < 2; j++) {
        int k = lane + 32 * j;
        load16(vb + (size_t)sKey[n][k] * 128, kv + k * 17);
    }
    __syncwarp();

#pragma unroll
    for (int rep = 0; rep < 2; rep++) {
        int jj = lane + 32 * rep;
        int tq = jj >> 4, d = jj & 15;
        float acc = 0.f;
#pragma unroll 8
        for (int k = 0; k < 64; k++) acc = fmaf(A[tq * 64 + k], kv[k * 17 + d], acc);
        int tok = (2 * Y + (tq >> 1)) * 32 + 2 * X + (tq & 1);
        g_msg1[((size_t)b * 1024 + tok) * 128 + n * 16 + d] = acc;
    }
}

// ---------------- level 2: final fine attention (8 parents -> 32 keys) -----
// grid = B*1024 quads, 256 threads (warp per head). Lane owns key=lane.
__global__ __launch_bounds__(256) void lvl2_kernel() {
    __shared__ float sKV[8][32 * 17];
    __shared__ float sAm[8][4 * 32];
    __shared__ float sQ [8][64];

    int blk = blockIdx.x;
    int L = blk & 1023, b = blk >> 10;
    int Y = L >> 5, X = L & 31;
    int n = threadIdx.x >> 5, lane = threadIdx.x & 31;
    float* kv = sKV[n];
    float* A  = sAm[n];
    float* Qs = sQ[n];

    int kp = lane >> 2, cj = lane & 3;
    size_t pb = (((size_t)b * 1024 + L) * 8 + n) * 8 + kp;
    float ps = g_ts1[pb];
    int   pi = g_ti1[pb];
    int key = ((pi >> 5) * 2 + (cj >> 1)) * 64 + (pi & 31) * 2 + (cj & 1);

    const float* kb = g_t2k + (size_t)b * 4096 * 128 + n * 16;
    load16(kb + (size_t)key * 128, kv + lane * 17);

    const float* qb = g_t2q + (size_t)b * 4096 * 128 + n * 16;
#pragma unroll
    for (int rep = 0; rep < 2; rep++) {
        int jj = lane + 32 * rep;
        int tq = jj >> 4, d = jj & 15;
        int tok = (2 * Y + (tq >> 1)) * 64 + 2 * X + (tq & 1);
        Qs[jj] = qb[(size_t)tok * 128 + d];
    }
    __syncwarp();

    float a[4];
#pragma unroll
    for (int tq = 0; tq < 4; tq++) {
        float acc = 0.f;
#pragma unroll
        for (int d = 0; d < 16; d++) acc = fmaf(Qs[tq * 16 + d], kv[lane * 17 + d], acc);
        a[tq] = acc * 0.25f;
    }
#pragma unroll
    for (int tq = 0; tq < 4; tq++) {
        float m = a[tq];
        m = fmaxf(m, __shfl_xor_sync(FULL, m, 1));
        m = fmaxf(m, __shfl_xor_sync(FULL, m, 2));
        float e = __expf(a[tq] - m);
        float s = e;
        s += __shfl_xor_sync(FULL, s, 1);
        s += __shfl_xor_sync(FULL, s, 2);
        A[tq * 32 + lane] = e / s * ps;   // final level: no masking, no topk needed
    }
    __syncwarp();

    const float* vb = g_t2v + (size_t)b * 4096 * 128 + n * 16;
    load16(vb + (size_t)key * 128, kv + lane * 17);
    __syncwarp();

#pragma unroll
    for (int rep = 0; rep < 2; rep++) {
        int jj = lane + 32 * rep;
        int tq = jj >> 4, d = jj & 15;
        float acc = 0.f;
#pragma unroll 8
        for (int k = 0; k < 32; k++) acc = fmaf(A[tq * 32 + k], kv[k * 17 + d], acc);
        int tok = (2 * Y + (tq >> 1)) * 64 + 2 * X + (tq & 1);
        g_msg2[((size_t)b * 4096 + tok) * 128 + n * 16 + d] = acc;
    }
}

// ---------------- fusion: upsample-sum all levels, write [B,C,64,64] -------
// grid = B*64 (one y-row), 256 threads
__global__ __launch_bounds__(256) void fuse_kernel(float* __restrict__ out) {
    __shared__ float sbuf[64 * 129];
    int b = blockIdx.x >> 6, y = blockIdx.x & 63;
    int t = threadIdx.x;
    const float* m0 = g_msg0 + ((size_t)b * 256  + (y >> 2) * 16) * 128;
    const float* m1 = g_msg1 + ((size_t)b * 1024 + (y >> 1) * 32) * 128;
    const float* m2 = g_msg2 + ((size_t)b * 4096 + y * 64) * 128;
#pragma unroll
    for (int i = 0; i < 32; i++) {
        int idx = i * 256 + t;
        int x = idx >> 7, c = idx & 127;
        sbuf[x * 129 + c] = (m0[(x >> 2) * 128 + c] + m1[(x >> 1) * 128 + c])
                            + m2[x * 128 + c];
    }
    __syncthreads();
    float* ob = out + (size_t)b * 128 * 4096 + (size_t)y * 64;
#pragma unroll
    for (int i = 0; i < 32; i++) {
        int idx = i * 256 + t;
        int c = idx >> 6, x = idx & 63;
        ob[(size_t)c * 4096 + x] = sbuf[x * 129 + c];
    }
}

// ---------------- launch ---------------------------------------------------
extern "C" void kernel_launch(void* const* d_in, const int* in_sizes, int n_in,
                              void* d_out, int out_size) {
    (void)in_sizes; (void)n_in; (void)out_size;
    const float* q0 = (const float*)d_in[0];
    const float* k0 = (const float*)d_in[1];
    const float* v0 = (const float*)d_in[2];
    const float* q1 = (const float*)d_in[3];
    const float* k1 = (const float*)d_in[4];
    const float* v1 = (const float*)d_in[5];
    const float* q2 = (const float*)d_in[6];
    const float* k2 = (const float*)d_in[7];
    const float* v2 = (const float*)d_in[8];

    dim3 tb(32, 8);
    transpose_kernel<<<dim3(32,  4, 4), tb>>>(q1, 0, 1024);
    transpose_kernel<<<dim3(32,  4, 4), tb>>>(k1, 1, 1024);
    transpose_kernel<<<dim3(32,  4, 4), tb>>>(v1, 2, 1024);
    transpose_kernel<<<dim3(128, 4, 4), tb>>>(q2, 3, 4096);
    transpose_kernel<<<dim3(128, 4, 4), tb>>>(k2, 4, 4096);
    transpose_kernel<<<dim3(128, 4, 4), tb>>>(v2, 5, 4096);

    lvl0_kernel<<<512, 256>>>(q0, k0, v0);
    lvl1_kernel<<<1024, 256>>>();
    lvl2_kernel<<<4096, 256>>>();
    fuse_kernel<<<256, 256>>>((float*)d_out);
}